// round 5
// baseline (speedup 1.0000x reference)
#include <cuda_runtime.h>
#include <cuda_fp16.h>
#include <cstdint>

#define BATCH 4
#define SEQ   4096
#define CH    1024
#define NH    16
#define HD    64
#define BS    64
#define NB    (SEQ / BS)          // 64
#define MROWS (BATCH * SEQ)       // 16384

// ---------------- scratch (device globals: allocation-free) ----------------
__device__ float g_Q[(size_t)MROWS * CH];
__device__ float g_K[(size_t)MROWS * CH];
__device__ float g_V[(size_t)MROWS * CH];
__device__ __half g_Ahi[(size_t)MROWS * CH];
__device__ __half g_Alo[(size_t)MROWS * CH];
__device__ __half g_Phi[(size_t)MROWS * CH];
__device__ __half g_Plo[(size_t)MROWS * CH];
__device__ __half g_Whi[(size_t)4 * CH * CH];

// =================== helpers ===================
__device__ __forceinline__ uint32_t smem_u32(const void* p) {
    uint32_t a;
    asm("{ .reg .u64 t; cvta.to.shared.u64 t, %1; cvt.u32.u64 %0, t; }"
        : "=r"(a) : "l"(p));
    return a;
}
__device__ __forceinline__ void cp16(uint32_t dst, const void* src) {
    asm volatile("cp.async.cg.shared.global [%0], [%1], 16;" :: "r"(dst), "l"(src));
}
__device__ __forceinline__ void cp_commit() {
    asm volatile("cp.async.commit_group;" ::: "memory");
}
template <int N>
__device__ __forceinline__ void cp_wait() {
    asm volatile("cp.async.wait_group %0;" :: "n"(N) : "memory");
}
__device__ __forceinline__ void ldsm4(uint32_t& r0, uint32_t& r1, uint32_t& r2,
                                      uint32_t& r3, uint32_t addr) {
    asm volatile("ldmatrix.sync.aligned.m8n8.x4.shared.b16 {%0,%1,%2,%3}, [%4];"
                 : "=r"(r0), "=r"(r1), "=r"(r2), "=r"(r3) : "r"(addr));
}
__device__ __forceinline__ void mma16816(float* c, const uint32_t* a,
                                         uint32_t b0, uint32_t b1) {
    asm volatile(
        "mma.sync.aligned.m16n8k16.row.col.f32.f16.f16.f32 "
        "{%0,%1,%2,%3}, {%4,%5,%6,%7}, {%8,%9}, {%0,%1,%2,%3};"
        : "+f"(c[0]), "+f"(c[1]), "+f"(c[2]), "+f"(c[3])
        : "r"(a[0]), "r"(a[1]), "r"(a[2]), "r"(a[3]), "r"(b0), "r"(b1));
}

// =================== fp32 -> fp16 hi/lo splitter ===================
__global__ __launch_bounds__(256) void split_f16(
    const float* __restrict__ in, __half* __restrict__ hi,
    __half* __restrict__ lo, int n)
{
    int i = (blockIdx.x * 256 + threadIdx.x) * 4;
    if (i >= n) return;
    float4 v = *(const float4*)(in + i);
    __half h0 = __float2half(v.x);
    __half h1 = __float2half(v.y);
    __half h2 = __float2half(v.z);
    __half h3 = __float2half(v.w);
    __half2 hp0; hp0.x = h0; hp0.y = h1;
    __half2 hp1; hp1.x = h2; hp1.y = h3;
    __half2 lp0; lp0.x = __float2half(v.x - __half2float(h0));
    lp0.y = __float2half(v.y - __half2float(h1));
    __half2 lp1; lp1.x = __float2half(v.z - __half2float(h2));
    lp1.y = __float2half(v.w - __half2float(h3));
    *(__half2*)(hi + i)     = hp0;
    *(__half2*)(hi + i + 2) = hp1;
    *(__half2*)(lo + i)     = lp0;
    *(__half2*)(lo + i + 2) = lp1;
}
__global__ __launch_bounds__(256) void to_f16(
    const float* __restrict__ in, __half* __restrict__ hi, int n)
{
    int i = (blockIdx.x * 256 + threadIdx.x) * 4;
    if (i >= n) return;
    float4 v = *(const float4*)(in + i);
    __half2 hp0; hp0.x = __float2half(v.x); hp0.y = __float2half(v.y);
    __half2 hp1; hp1.x = __float2half(v.z); hp1.y = __float2half(v.w);
    *(__half2*)(hi + i)     = hp0;
    *(__half2*)(hi + i + 2) = hp1;
}

// =================== HMMA GEMM: Out = A@W^T + bias (A=fp16x2, W=fp16) =======
// BM=BN=128, BK=32 halfs, 3-stage cp.async, 4 warps, warp tile 64x64.
#define BKH 32
#define NKC (CH / BKH)            // 32
#define HT_BYTES 8192             // 128 rows * 64B
#define HSTAGE (3 * HT_BYTES)     // Ahi, Alo, Bh
#define HGEMM_SMEM (3 * HSTAGE)   // 73728

__device__ __forceinline__ uint32_t sw_off(int row, int chunk) {
    return (uint32_t)(row * 64 + ((chunk ^ ((row >> 1) & 3)) << 4));
}

__global__ __launch_bounds__(128) void gemm_hmma(
    const __half* __restrict__ Ahi, const __half* __restrict__ Alo,
    const __half* __restrict__ Bh,
    const float* __restrict__ bias, float* __restrict__ Out)
{
    extern __shared__ char dsm[];
    const uint32_t base = smem_u32(dsm);

    const int tid  = threadIdx.x;
    const int wid  = tid >> 5;     // 0..3
    const int lane = tid & 31;
    const int bm = blockIdx.y * 128;
    const int bn = blockIdx.x * 128;
    const int wm = (wid & 1) * 64;
    const int wn = (wid >> 1) * 64;

    const __half* srcs[3] = {
        Ahi + (size_t)bm * CH, Alo + (size_t)bm * CH, Bh + (size_t)bn * CH };

    auto load_stage = [&](int st, int kc) {
        const uint32_t sb = base + st * HSTAGE;
#pragma unroll
        for (int p = 0; p < 12; p++) {
            int idx = p * 128 + tid;       // 0..1535
            int buf = idx >> 9;            // 0..2
            int rem = idx & 511;
            int row = rem >> 2;            // 0..127
            int ch  = rem & 3;
            const __half* s = srcs[buf] + (size_t)row * CH + kc * BKH + ch * 8;
            cp16(sb + buf * HT_BYTES + sw_off(row, ch), s);
        }
        cp_commit();
    };

    float acc[4][8][4];
#pragma unroll
    for (int mi = 0; mi < 4; mi++)
#pragma unroll
        for (int ni = 0; ni < 8; ni++)
#pragma unroll
            for (int t = 0; t < 4; t++) acc[mi][ni][t] = 0.0f;

    load_stage(0, 0);
    load_stage(1, 1);

    const int lr = lane & 15;
    const int lc = lane >> 4;

    for (int kc = 0; kc < NKC; kc++) {
        if (kc < NKC - 1) cp_wait<1>(); else cp_wait<0>();
        __syncthreads();

        const uint32_t sb = base + (kc % 3) * HSTAGE;
        const uint32_t aHib = sb;
        const uint32_t aLob = sb + HT_BYTES;
        const uint32_t bHib = sb + 2 * HT_BYTES;

#pragma unroll
        for (int ks = 0; ks < 2; ks++) {
            const int chnk = ks * 2 + lc;
            uint32_t ah[4][4], al[4][4], bh[4][4];
#pragma unroll
            for (int mi = 0; mi < 4; mi++) {
                uint32_t off = sw_off(wm + mi * 16 + lr, chnk);
                ldsm4(ah[mi][0], ah[mi][1], ah[mi][2], ah[mi][3], aHib + off);
                ldsm4(al[mi][0], al[mi][1], al[mi][2], al[mi][3], aLob + off);
            }
#pragma unroll
            for (int g = 0; g < 4; g++) {
                uint32_t off = sw_off(wn + g * 16 + lr, chnk);
                ldsm4(bh[g][0], bh[g][1], bh[g][2], bh[g][3], bHib + off);
            }
#pragma unroll
            for (int mi = 0; mi < 4; mi++)
#pragma unroll
                for (int ni = 0; ni < 8; ni++) {
                    const int g = ni >> 1, w = ni & 1;
                    mma16816(acc[mi][ni], ah[mi], bh[g][w], bh[g][w + 2]);
                    mma16816(acc[mi][ni], al[mi], bh[g][w], bh[g][w + 2]);
                }
        }
        if (kc + 2 < NKC) load_stage((kc + 2) % 3, kc + 2);
    }

#pragma unroll
    for (int mi = 0; mi < 4; mi++) {
        const int r0 = bm + wm + mi * 16 + (lane >> 2);
#pragma unroll
        for (int ni = 0; ni < 8; ni++) {
            const int c = bn + wn + ni * 8 + (lane & 3) * 2;
            const float b0 = bias[c], b1 = bias[c + 1];
            float2 v0 = make_float2(acc[mi][ni][0] + b0, acc[mi][ni][1] + b1);
            float2 v1 = make_float2(acc[mi][ni][2] + b0, acc[mi][ni][3] + b1);
            *(float2*)(Out + (size_t)r0 * CH + c)       = v0;
            *(float2*)(Out + (size_t)(r0 + 8) * CH + c) = v1;
        }
    }
}

// ---------------- attention: one CTA per (block n, head h, batch b) --------
#define QT_STRIDE 68
#define KT_STRIDE 196
#define VS_STRIDE 68
#define PS_STRIDE 196
#define QT_OFF 0
#define KV_OFF (64 * QT_STRIDE)
#define KV_FLOATS 13056
#define PS_OFF (KV_OFF + KV_FLOATS)
#define SMEM_FLOATS (PS_OFF + (64 * PS_STRIDE + 1) / 2)
#define ATTN_SMEM_BYTES (SMEM_FLOATS * 4)        // 94720

__global__ __launch_bounds__(256, 2) void attn_kernel(
    const float* __restrict__ Q, const float* __restrict__ K,
    const float* __restrict__ V,
    __half* __restrict__ Ohi, __half* __restrict__ Olo)
{
    extern __shared__ float sm[];
    float*  qT  = sm + QT_OFF;
    float*  kT  = sm + KV_OFF;
    float*  vs  = sm + KV_OFF;
    __half* Ps  = (__half*)(sm + PS_OFF);

    const int tid = threadIdx.x;
    const int n = blockIdx.x;
    const int h = blockIdx.y;
    const int b = blockIdx.z;
    const size_t base = (size_t)b * SEQ * CH + (size_t)h * HD;

#pragma unroll
    for (int p = 0; p < 4; p++) {
        int idx = tid + p * 256;
        int i   = idx >> 4;
        int dd0 = (idx & 15) << 2;
        float4 v4 = *(const float4*)(Q + base + (size_t)(n * BS + i) * CH + dd0);
        qT[(dd0 + 0) * QT_STRIDE + i] = v4.x;
        qT[(dd0 + 1) * QT_STRIDE + i] = v4.y;
        qT[(dd0 + 2) * QT_STRIDE + i] = v4.z;
        qT[(dd0 + 3) * QT_STRIDE + i] = v4.w;
    }
#pragma unroll
    for (int p = 0; p < 12; p++) {
        int idx = tid + p * 256;
        int j   = idx >> 4;
        int dd0 = (idx & 15) << 2;
        int kpos = (n - 1) * BS + j;
        float4 v4 = make_float4(0.f, 0.f, 0.f, 0.f);
        if (kpos >= 0 && kpos < SEQ)
            v4 = *(const float4*)(K + base + (size_t)kpos * CH + dd0);
        kT[(dd0 + 0) * KT_STRIDE + j] = v4.x;
        kT[(dd0 + 1) * KT_STRIDE + j] = v4.y;
        kT[(dd0 + 2) * KT_STRIDE + j] = v4.z;
        kT[(dd0 + 3) * KT_STRIDE + j] = v4.w;
    }
    __syncthreads();

    const int i0 = (tid >> 4) << 2;
    const int j0 = (tid & 15) * 12;
    float acc[4][12];
#pragma unroll
    for (int ii = 0; ii < 4; ii++)
#pragma unroll
        for (int jj = 0; jj < 12; jj++) acc[ii][jj] = 0.0f;

#pragma unroll 4
    for (int dd = 0; dd < 64; dd++) {
        float4 a4 = *(const float4*)&qT[dd * QT_STRIDE + i0];
        float4 b0 = *(const float4*)&kT[dd * KT_STRIDE + j0];
        float4 b1 = *(const float4*)&kT[dd * KT_STRIDE + j0 + 4];
        float4 b2 = *(const float4*)&kT[dd * KT_STRIDE + j0 + 8];
        float a[4] = {a4.x, a4.y, a4.z, a4.w};
        float bb[12] = {b0.x, b0.y, b0.z, b0.w, b1.x, b1.y, b1.z, b1.w,
                        b2.x, b2.y, b2.z, b2.w};
#pragma unroll
        for (int ii = 0; ii < 4; ii++)
#pragma unroll
            for (int jj = 0; jj < 12; jj++)
                acc[ii][jj] += a[ii] * bb[jj];
    }

    const float scale = 0.125f;
    float mrow[4] = {-1e30f, -1e30f, -1e30f, -1e30f};
#pragma unroll
    for (int ii = 0; ii < 4; ii++) {
        const int i = i0 + ii;
#pragma unroll
        for (int jj = 0; jj < 12; jj++) {
            const int j = j0 + jj;
            bool valid = (j <= i + BS) &&
                         (n > 0 || j >= BS) &&
                         (n < NB - 1 || j < 2 * BS);
            acc[ii][jj] = valid ? acc[ii][jj] * scale : -1e30f;
            mrow[ii] = fmaxf(mrow[ii], acc[ii][jj]);
        }
    }
#pragma unroll
    for (int ii = 0; ii < 4; ii++) {
        mrow[ii] = fmaxf(mrow[ii], __shfl_xor_sync(0xffffffffu, mrow[ii], 1));
        mrow[ii] = fmaxf(mrow[ii], __shfl_xor_sync(0xffffffffu, mrow[ii], 2));
        mrow[ii] = fmaxf(mrow[ii], __shfl_xor_sync(0xffffffffu, mrow[ii], 4));
        mrow[ii] = fmaxf(mrow[ii], __shfl_xor_sync(0xffffffffu, mrow[ii], 8));
    }
    float srow[4] = {0.f, 0.f, 0.f, 0.f};
#pragma unroll
    for (int ii = 0; ii < 4; ii++)
#pragma unroll
        for (int jj = 0; jj < 12; jj++) {
            acc[ii][jj] = __expf(acc[ii][jj] - mrow[ii]);
            srow[ii] += acc[ii][jj];
        }
#pragma unroll
    for (int ii = 0; ii < 4; ii++) {
        srow[ii] += __shfl_xor_sync(0xffffffffu, srow[ii], 1);
        srow[ii] += __shfl_xor_sync(0xffffffffu, srow[ii], 2);
        srow[ii] += __shfl_xor_sync(0xffffffffu, srow[ii], 4);
        srow[ii] += __shfl_xor_sync(0xffffffffu, srow[ii], 8);
        const float inv = 1.0f / srow[ii];
#pragma unroll
        for (int jj = 0; jj < 12; jj++)
            Ps[(i0 + ii) * PS_STRIDE + j0 + jj] = __float2half(acc[ii][jj] * inv);
    }
    __syncthreads();

#pragma unroll
    for (int p = 0; p < 12; p++) {
        int idx = tid + p * 256;
        int j   = idx >> 4;
        int dd0 = (idx & 15) << 2;
        int kpos = (n - 1) * BS + j;
        float4 v4 = make_float4(0.f, 0.f, 0.f, 0.f);
        if (kpos >= 0 && kpos < SEQ)
            v4 = *(const float4*)(V + base + (size_t)kpos * CH + dd0);
        *(float4*)&vs[j * VS_STRIDE + dd0] = v4;
    }
    __syncthreads();

    const int c0 = (tid & 15) << 2;
    float o[4][4];
#pragma unroll
    for (int ii = 0; ii < 4; ii++)
#pragma unroll
        for (int cc = 0; cc < 4; cc++) o[ii][cc] = 0.0f;

#pragma unroll 4
    for (int j = 0; j < 192; j++) {
        float4 v4 = *(const float4*)&vs[j * VS_STRIDE + c0];
        float p0 = __half2float(Ps[(i0 + 0) * PS_STRIDE + j]);
        float p1 = __half2float(Ps[(i0 + 1) * PS_STRIDE + j]);
        float p2 = __half2float(Ps[(i0 + 2) * PS_STRIDE + j]);
        float p3 = __half2float(Ps[(i0 + 3) * PS_STRIDE + j]);
        o[0][0] += p0 * v4.x; o[0][1] += p0 * v4.y; o[0][2] += p0 * v4.z; o[0][3] += p0 * v4.w;
        o[1][0] += p1 * v4.x; o[1][1] += p1 * v4.y; o[1][2] += p1 * v4.z; o[1][3] += p1 * v4.w;
        o[2][0] += p2 * v4.x; o[2][1] += p2 * v4.y; o[2][2] += p2 * v4.z; o[2][3] += p2 * v4.w;
        o[3][0] += p3 * v4.x; o[3][1] += p3 * v4.y; o[3][2] += p3 * v4.z; o[3][3] += p3 * v4.w;
    }
#pragma unroll
    for (int ii = 0; ii < 4; ii++) {
        const size_t oidx = base + (size_t)(n * BS + i0 + ii) * CH + c0;
        __half h0 = __float2half(o[ii][0]);
        __half h1 = __float2half(o[ii][1]);
        __half h2 = __float2half(o[ii][2]);
        __half h3 = __float2half(o[ii][3]);
        __half2 hp0; hp0.x = h0; hp0.y = h1;
        __half2 hp1; hp1.x = h2; hp1.y = h3;
        __half2 lp0, lp1;
        lp0.x = __float2half(o[ii][0] - __half2float(h0));
        lp0.y = __float2half(o[ii][1] - __half2float(h1));
        lp1.x = __float2half(o[ii][2] - __half2float(h2));
        lp1.y = __float2half(o[ii][3] - __half2float(h3));
        *(__half2*)(Ohi + oidx)     = hp0;
        *(__half2*)(Ohi + oidx + 2) = hp1;
        *(__half2*)(Olo + oidx)     = lp0;
        *(__half2*)(Olo + oidx + 2) = lp1;
    }
}

// ---------------------------------------------------------------------------
extern "C" void kernel_launch(void* const* d_in, const int* in_sizes, int n_in,
                              void* d_out, int out_size)
{
    const float* x  = (const float*)d_in[0];
    const float* Wq = (const float*)d_in[1];
    const float* bq = (const float*)d_in[2];
    const float* Wk = (const float*)d_in[3];
    const float* bk = (const float*)d_in[4];
    const float* Wv = (const float*)d_in[5];
    const float* bv = (const float*)d_in[6];
    const float* Wo = (const float*)d_in[7];
    const float* bo = (const float*)d_in[8];
    float* out = (float*)d_out;

    float *qp, *kp, *vp;
    __half *ahi, *alo, *phi, *plo, *whi;
    cudaGetSymbolAddress((void**)&qp,  g_Q);
    cudaGetSymbolAddress((void**)&kp,  g_K);
    cudaGetSymbolAddress((void**)&vp,  g_V);
    cudaGetSymbolAddress((void**)&ahi, g_Ahi);
    cudaGetSymbolAddress((void**)&alo, g_Alo);
    cudaGetSymbolAddress((void**)&phi, g_Phi);
    cudaGetSymbolAddress((void**)&plo, g_Plo);
    cudaGetSymbolAddress((void**)&whi, g_Whi);

    cudaFuncSetAttribute(attn_kernel,
                         cudaFuncAttributeMaxDynamicSharedMemorySize, ATTN_SMEM_BYTES);
    cudaFuncSetAttribute(gemm_hmma,
                         cudaFuncAttributeMaxDynamicSharedMemorySize, HGEMM_SMEM);

    const int NX = MROWS * CH;
    const int NW = CH * CH;

    split_f16<<<NX / 1024, 256>>>(x, ahi, alo, NX);
    to_f16<<<NW / 1024, 256>>>(Wq, whi + 0 * (size_t)NW, NW);
    to_f16<<<NW / 1024, 256>>>(Wk, whi + 1 * (size_t)NW, NW);
    to_f16<<<NW / 1024, 256>>>(Wv, whi + 2 * (size_t)NW, NW);
    to_f16<<<NW / 1024, 256>>>(Wo, whi + 3 * (size_t)NW, NW);

    dim3 ggrid(CH / 128, MROWS / 128);   // (8, 128)
    gemm_hmma<<<ggrid, 128, HGEMM_SMEM>>>(ahi, alo, whi + 0 * (size_t)NW, bq, qp);
    gemm_hmma<<<ggrid, 128, HGEMM_SMEM>>>(ahi, alo, whi + 1 * (size_t)NW, bk, kp);
    gemm_hmma<<<ggrid, 128, HGEMM_SMEM>>>(ahi, alo, whi + 2 * (size_t)NW, bv, vp);

    attn_kernel<<<dim3(NB, NH, BATCH), 256, ATTN_SMEM_BYTES>>>(qp, kp, vp, phi, plo);

    gemm_hmma<<<ggrid, 128, HGEMM_SMEM>>>(phi, plo, whi + 3 * (size_t)NW, bo, out);
}

// round 6
// speedup vs baseline: 1.1077x; 1.1077x over previous
#include <cuda_runtime.h>
#include <cuda_fp16.h>
#include <cstdint>

#define BATCH 4
#define SEQ   4096
#define CH    1024
#define NH    16
#define HD    64
#define BS    64
#define NB    (SEQ / BS)          // 64
#define MROWS (BATCH * SEQ)       // 16384

// ---------------- scratch (device globals: allocation-free) ----------------
__device__ float g_Q[(size_t)MROWS * CH];
__device__ float g_K[(size_t)MROWS * CH];
__device__ float g_V[(size_t)MROWS * CH];
__device__ __half g_Ahi[(size_t)MROWS * CH];
__device__ __half g_Alo[(size_t)MROWS * CH];
__device__ __half g_Phi[(size_t)MROWS * CH];
__device__ __half g_Plo[(size_t)MROWS * CH];
__device__ __half g_Whi[(size_t)4 * CH * CH];

// =================== helpers ===================
__device__ __forceinline__ uint32_t smem_u32(const void* p) {
    uint32_t a;
    asm("{ .reg .u64 t; cvta.to.shared.u64 t, %1; cvt.u32.u64 %0, t; }"
        : "=r"(a) : "l"(p));
    return a;
}
__device__ __forceinline__ void cp16(uint32_t dst, const void* src) {
    asm volatile("cp.async.cg.shared.global [%0], [%1], 16;" :: "r"(dst), "l"(src));
}
__device__ __forceinline__ void cp_commit() {
    asm volatile("cp.async.commit_group;" ::: "memory");
}
template <int N>
__device__ __forceinline__ void cp_wait() {
    asm volatile("cp.async.wait_group %0;" :: "n"(N) : "memory");
}
__device__ __forceinline__ void ldsm4(uint32_t& r0, uint32_t& r1, uint32_t& r2,
                                      uint32_t& r3, uint32_t addr) {
    asm volatile("ldmatrix.sync.aligned.m8n8.x4.shared.b16 {%0,%1,%2,%3}, [%4];"
                 : "=r"(r0), "=r"(r1), "=r"(r2), "=r"(r3) : "r"(addr));
}
__device__ __forceinline__ void mma16816(float* c, const uint32_t* a,
                                         uint32_t b0, uint32_t b1) {
    asm volatile(
        "mma.sync.aligned.m16n8k16.row.col.f32.f16.f16.f32 "
        "{%0,%1,%2,%3}, {%4,%5,%6,%7}, {%8,%9}, {%0,%1,%2,%3};"
        : "+f"(c[0]), "+f"(c[1]), "+f"(c[2]), "+f"(c[3])
        : "r"(a[0]), "r"(a[1]), "r"(a[2]), "r"(a[3]), "r"(b0), "r"(b1));
}

// =================== fp32 -> fp16 hi/lo splitter ===================
__global__ __launch_bounds__(256) void split_f16(
    const float* __restrict__ in, __half* __restrict__ hi,
    __half* __restrict__ lo, int n)
{
    int i = (blockIdx.x * 256 + threadIdx.x) * 4;
    if (i >= n) return;
    float4 v = *(const float4*)(in + i);
    __half h0 = __float2half(v.x);
    __half h1 = __float2half(v.y);
    __half h2 = __float2half(v.z);
    __half h3 = __float2half(v.w);
    __half2 hp0; hp0.x = h0; hp0.y = h1;
    __half2 hp1; hp1.x = h2; hp1.y = h3;
    __half2 lp0; lp0.x = __float2half(v.x - __half2float(h0));
    lp0.y = __float2half(v.y - __half2float(h1));
    __half2 lp1; lp1.x = __float2half(v.z - __half2float(h2));
    lp1.y = __float2half(v.w - __half2float(h3));
    *(__half2*)(hi + i)     = hp0;
    *(__half2*)(hi + i + 2) = hp1;
    *(__half2*)(lo + i)     = lp0;
    *(__half2*)(lo + i + 2) = lp1;
}
__global__ __launch_bounds__(256) void to_f16(
    const float* __restrict__ in, __half* __restrict__ hi, int n)
{
    int i = (blockIdx.x * 256 + threadIdx.x) * 4;
    if (i >= n) return;
    float4 v = *(const float4*)(in + i);
    __half2 hp0; hp0.x = __float2half(v.x); hp0.y = __float2half(v.y);
    __half2 hp1; hp1.x = __float2half(v.z); hp1.y = __float2half(v.w);
    *(__half2*)(hi + i)     = hp0;
    *(__half2*)(hi + i + 2) = hp1;
}

// =================== HMMA GEMM: Out = A@W^T + bias (A=fp16x2, W=fp16) =======
// BM=BN=128, BK=32 halfs, 3-stage cp.async, 8 warps (32x64 warp tiles), 2 CTA/SM.
#define BKH 32
#define NKC (CH / BKH)            // 32
#define HT_BYTES 8192             // 128 rows * 64B
#define HSTAGE (3 * HT_BYTES)     // Ahi, Alo, Bh
#define HGEMM_SMEM (3 * HSTAGE)   // 73728

__device__ __forceinline__ uint32_t sw_off(int row, int chunk) {
    return (uint32_t)(row * 64 + ((chunk ^ ((row >> 1) & 3)) << 4));
}

__global__ __launch_bounds__(256, 2) void gemm_hmma(
    const __half* __restrict__ Ahi, const __half* __restrict__ Alo,
    const __half* __restrict__ Bh,
    const float* __restrict__ bias, float* __restrict__ Out)
{
    extern __shared__ char dsm[];
    const uint32_t base = smem_u32(dsm);

    const int tid  = threadIdx.x;
    const int wid  = tid >> 5;
    const int lane = tid & 31;
    const int bm = blockIdx.y * 128;
    const int bn = blockIdx.x * 128;
    const int wm = (wid & 3) * 32;
    const int wn = (wid >> 2) * 64;

    const __half* srcs[3] = {
        Ahi + (size_t)bm * CH, Alo + (size_t)bm * CH, Bh + (size_t)bn * CH };

    auto load_stage = [&](int st, int kc) {
        const uint32_t sb = base + st * HSTAGE;
#pragma unroll
        for (int p = 0; p < 6; p++) {
            int idx = p * 256 + tid;       // 0..1535
            int buf = idx >> 9;            // 0..2
            int rem = idx & 511;
            int row = rem >> 2;            // 0..127
            int ch  = rem & 3;
            const __half* s = srcs[buf] + (size_t)row * CH + kc * BKH + ch * 8;
            cp16(sb + buf * HT_BYTES + sw_off(row, ch), s);
        }
        cp_commit();
    };

    float acc[2][8][4];
#pragma unroll
    for (int mi = 0; mi < 2; mi++)
#pragma unroll
        for (int ni = 0; ni < 8; ni++)
#pragma unroll
            for (int t = 0; t < 4; t++) acc[mi][ni][t] = 0.0f;

    load_stage(0, 0);
    load_stage(1, 1);

    const int lr = lane & 15;
    const int lc = lane >> 4;

    for (int kc = 0; kc < NKC; kc++) {
        if (kc < NKC - 1) cp_wait<1>(); else cp_wait<0>();
        __syncthreads();

        const uint32_t sb = base + (kc % 3) * HSTAGE;
        const uint32_t aHib = sb;
        const uint32_t aLob = sb + HT_BYTES;
        const uint32_t bHib = sb + 2 * HT_BYTES;

#pragma unroll
        for (int ks = 0; ks < 2; ks++) {
            const int chnk = ks * 2 + lc;
            uint32_t ah[2][4], al[2][4], bh[4][4];
#pragma unroll
            for (int mi = 0; mi < 2; mi++) {
                uint32_t off = sw_off(wm + mi * 16 + lr, chnk);
                ldsm4(ah[mi][0], ah[mi][1], ah[mi][2], ah[mi][3], aHib + off);
                ldsm4(al[mi][0], al[mi][1], al[mi][2], al[mi][3], aLob + off);
            }
#pragma unroll
            for (int g = 0; g < 4; g++) {
                uint32_t off = sw_off(wn + g * 16 + lr, chnk);
                ldsm4(bh[g][0], bh[g][1], bh[g][2], bh[g][3], bHib + off);
            }
#pragma unroll
            for (int mi = 0; mi < 2; mi++)
#pragma unroll
                for (int ni = 0; ni < 8; ni++) {
                    const int g = ni >> 1, w = ni & 1;
                    mma16816(acc[mi][ni], ah[mi], bh[g][w], bh[g][w + 2]);
                    mma16816(acc[mi][ni], al[mi], bh[g][w], bh[g][w + 2]);
                }
        }
        if (kc + 2 < NKC) load_stage((kc + 2) % 3, kc + 2);
    }

#pragma unroll
    for (int mi = 0; mi < 2; mi++) {
        const int r0 = bm + wm + mi * 16 + (lane >> 2);
#pragma unroll
        for (int ni = 0; ni < 8; ni++) {
            const int c = bn + wn + ni * 8 + (lane & 3) * 2;
            const float b0 = bias[c], b1 = bias[c + 1];
            float2 v0 = make_float2(acc[mi][ni][0] + b0, acc[mi][ni][1] + b1);
            float2 v1 = make_float2(acc[mi][ni][2] + b0, acc[mi][ni][3] + b1);
            *(float2*)(Out + (size_t)r0 * CH + c)       = v0;
            *(float2*)(Out + (size_t)(r0 + 8) * CH + c) = v1;
        }
    }
}

// ---------------- attention: 128-col window (blocks n-1, n only) -----------
// The n+1 block is always fully masked by causality (j>=128 needs i>=64).
// smem: qT[64][68] f32; kv region (kT[64][132] -> vs[128][68]) f32; Ps[64][132] f16
#define QT_STRIDE 68
#define KT_STRIDE 132
#define VS_STRIDE 68
#define PS_STRIDE 132
#define WIN 128
#define QT_OFF 0
#define KV_OFF (64 * QT_STRIDE)                  // 4352
#define KV_FLOATS 8704                            // max(64*132, 128*68)
#define PS_OFF (KV_OFF + KV_FLOATS)               // 13056
#define SMEM_FLOATS (PS_OFF + (64 * PS_STRIDE) / 2)  // +4224 = 17280
#define ATTN_SMEM_BYTES (SMEM_FLOATS * 4)         // 69120

__global__ __launch_bounds__(256, 2) void attn_kernel(
    const float* __restrict__ Q, const float* __restrict__ K,
    const float* __restrict__ V,
    __half* __restrict__ Ohi, __half* __restrict__ Olo)
{
    extern __shared__ float sm[];
    float*  qT  = sm + QT_OFF;
    float*  kT  = sm + KV_OFF;
    float*  vs  = sm + KV_OFF;
    __half* Ps  = (__half*)(sm + PS_OFF);

    const int tid = threadIdx.x;
    const int n = blockIdx.x;
    const int h = blockIdx.y;
    const int b = blockIdx.z;
    const size_t base = (size_t)b * SEQ * CH + (size_t)h * HD;

    // q transposed
#pragma unroll
    for (int p = 0; p < 4; p++) {
        int idx = tid + p * 256;
        int i   = idx >> 4;
        int dd0 = (idx & 15) << 2;
        float4 v4 = *(const float4*)(Q + base + (size_t)(n * BS + i) * CH + dd0);
        qT[(dd0 + 0) * QT_STRIDE + i] = v4.x;
        qT[(dd0 + 1) * QT_STRIDE + i] = v4.y;
        qT[(dd0 + 2) * QT_STRIDE + i] = v4.z;
        qT[(dd0 + 3) * QT_STRIDE + i] = v4.w;
    }
    // k window: 128 rows, kpos = (n-1)*64 + j
#pragma unroll
    for (int p = 0; p < 8; p++) {
        int idx = tid + p * 256;
        int j   = idx >> 4;              // 0..127
        int dd0 = (idx & 15) << 2;
        int kpos = (n - 1) * BS + j;
        float4 v4 = make_float4(0.f, 0.f, 0.f, 0.f);
        if (kpos >= 0)
            v4 = *(const float4*)(K + base + (size_t)kpos * CH + dd0);
        kT[(dd0 + 0) * KT_STRIDE + j] = v4.x;
        kT[(dd0 + 1) * KT_STRIDE + j] = v4.y;
        kT[(dd0 + 2) * KT_STRIDE + j] = v4.z;
        kT[(dd0 + 3) * KT_STRIDE + j] = v4.w;
    }
    __syncthreads();

    const int i0 = (tid >> 4) << 2;      // 4 rows
    const int j0 = (tid & 15) << 3;      // 8 cols
    float acc[4][8];
#pragma unroll
    for (int ii = 0; ii < 4; ii++)
#pragma unroll
        for (int jj = 0; jj < 8; jj++) acc[ii][jj] = 0.0f;

#pragma unroll 4
    for (int dd = 0; dd < 64; dd++) {
        float4 a4 = *(const float4*)&qT[dd * QT_STRIDE + i0];
        float4 b0 = *(const float4*)&kT[dd * KT_STRIDE + j0];
        float4 b1 = *(const float4*)&kT[dd * KT_STRIDE + j0 + 4];
        float a[4] = {a4.x, a4.y, a4.z, a4.w};
        float bb[8] = {b0.x, b0.y, b0.z, b0.w, b1.x, b1.y, b1.z, b1.w};
#pragma unroll
        for (int ii = 0; ii < 4; ii++)
#pragma unroll
            for (int jj = 0; jj < 8; jj++)
                acc[ii][jj] += a[ii] * bb[jj];
    }

    const float scale = 0.125f;
    float mrow[4] = {-1e30f, -1e30f, -1e30f, -1e30f};
#pragma unroll
    for (int ii = 0; ii < 4; ii++) {
        const int i = i0 + ii;
#pragma unroll
        for (int jj = 0; jj < 8; jj++) {
            const int j = j0 + jj;
            bool valid = (j <= i + BS) && (n > 0 || j >= BS);
            acc[ii][jj] = valid ? acc[ii][jj] * scale : -1e30f;
            mrow[ii] = fmaxf(mrow[ii], acc[ii][jj]);
        }
    }
#pragma unroll
    for (int ii = 0; ii < 4; ii++) {
        mrow[ii] = fmaxf(mrow[ii], __shfl_xor_sync(0xffffffffu, mrow[ii], 1));
        mrow[ii] = fmaxf(mrow[ii], __shfl_xor_sync(0xffffffffu, mrow[ii], 2));
        mrow[ii] = fmaxf(mrow[ii], __shfl_xor_sync(0xffffffffu, mrow[ii], 4));
        mrow[ii] = fmaxf(mrow[ii], __shfl_xor_sync(0xffffffffu, mrow[ii], 8));
    }
    float srow[4] = {0.f, 0.f, 0.f, 0.f};
#pragma unroll
    for (int ii = 0; ii < 4; ii++)
#pragma unroll
        for (int jj = 0; jj < 8; jj++) {
            acc[ii][jj] = __expf(acc[ii][jj] - mrow[ii]);
            srow[ii] += acc[ii][jj];
        }
#pragma unroll
    for (int ii = 0; ii < 4; ii++) {
        srow[ii] += __shfl_xor_sync(0xffffffffu, srow[ii], 1);
        srow[ii] += __shfl_xor_sync(0xffffffffu, srow[ii], 2);
        srow[ii] += __shfl_xor_sync(0xffffffffu, srow[ii], 4);
        srow[ii] += __shfl_xor_sync(0xffffffffu, srow[ii], 8);
        const float inv = 1.0f / srow[ii];
#pragma unroll
        for (int jj = 0; jj < 8; jj++)
            Ps[(i0 + ii) * PS_STRIDE + j0 + jj] = __float2half(acc[ii][jj] * inv);
    }
    __syncthreads();

    // v window over kT region
#pragma unroll
    for (int p = 0; p < 8; p++) {
        int idx = tid + p * 256;
        int j   = idx >> 4;
        int dd0 = (idx & 15) << 2;
        int kpos = (n - 1) * BS + j;
        float4 v4 = make_float4(0.f, 0.f, 0.f, 0.f);
        if (kpos >= 0)
            v4 = *(const float4*)(V + base + (size_t)kpos * CH + dd0);
        *(float4*)&vs[j * VS_STRIDE + dd0] = v4;
    }
    __syncthreads();

    const int c0 = (tid & 15) << 2;
    float o[4][4];
#pragma unroll
    for (int ii = 0; ii < 4; ii++)
#pragma unroll
        for (int cc = 0; cc < 4; cc++) o[ii][cc] = 0.0f;

    // beyond j = i0+3+64 all four rows' P are exactly 0 -> early exit
    const int jlim = (i0 + 68 < WIN) ? (i0 + 68) : WIN;
#pragma unroll 4
    for (int j = 0; j < jlim; j++) {
        float4 v4 = *(const float4*)&vs[j * VS_STRIDE + c0];
        float p0 = __half2float(Ps[(i0 + 0) * PS_STRIDE + j]);
        float p1 = __half2float(Ps[(i0 + 1) * PS_STRIDE + j]);
        float p2 = __half2float(Ps[(i0 + 2) * PS_STRIDE + j]);
        float p3 = __half2float(Ps[(i0 + 3) * PS_STRIDE + j]);
        o[0][0] += p0 * v4.x; o[0][1] += p0 * v4.y; o[0][2] += p0 * v4.z; o[0][3] += p0 * v4.w;
        o[1][0] += p1 * v4.x; o[1][1] += p1 * v4.y; o[1][2] += p1 * v4.z; o[1][3] += p1 * v4.w;
        o[2][0] += p2 * v4.x; o[2][1] += p2 * v4.y; o[2][2] += p2 * v4.z; o[2][3] += p2 * v4.w;
        o[3][0] += p3 * v4.x; o[3][1] += p3 * v4.y; o[3][2] += p3 * v4.z; o[3][3] += p3 * v4.w;
    }
#pragma unroll
    for (int ii = 0; ii < 4; ii++) {
        const size_t oidx = base + (size_t)(n * BS + i0 + ii) * CH + c0;
        __half h0 = __float2half(o[ii][0]);
        __half h1 = __float2half(o[ii][1]);
        __half h2 = __float2half(o[ii][2]);
        __half h3 = __float2half(o[ii][3]);
        __half2 hp0; hp0.x = h0; hp0.y = h1;
        __half2 hp1; hp1.x = h2; hp1.y = h3;
        __half2 lp0, lp1;
        lp0.x = __float2half(o[ii][0] - __half2float(h0));
        lp0.y = __float2half(o[ii][1] - __half2float(h1));
        lp1.x = __float2half(o[ii][2] - __half2float(h2));
        lp1.y = __float2half(o[ii][3] - __half2float(h3));
        *(__half2*)(Ohi + oidx)     = hp0;
        *(__half2*)(Ohi + oidx + 2) = hp1;
        *(__half2*)(Olo + oidx)     = lp0;
        *(__half2*)(Olo + oidx + 2) = lp1;
    }
}

// ---------------------------------------------------------------------------
extern "C" void kernel_launch(void* const* d_in, const int* in_sizes, int n_in,
                              void* d_out, int out_size)
{
    const float* x  = (const float*)d_in[0];
    const float* Wq = (const float*)d_in[1];
    const float* bq = (const float*)d_in[2];
    const float* Wk = (const float*)d_in[3];
    const float* bk = (const float*)d_in[4];
    const float* Wv = (const float*)d_in[5];
    const float* bv = (const float*)d_in[6];
    const float* Wo = (const float*)d_in[7];
    const float* bo = (const float*)d_in[8];
    float* out = (float*)d_out;

    float *qp, *kp, *vp;
    __half *ahi, *alo, *phi, *plo, *whi;
    cudaGetSymbolAddress((void**)&qp,  g_Q);
    cudaGetSymbolAddress((void**)&kp,  g_K);
    cudaGetSymbolAddress((void**)&vp,  g_V);
    cudaGetSymbolAddress((void**)&ahi, g_Ahi);
    cudaGetSymbolAddress((void**)&alo, g_Alo);
    cudaGetSymbolAddress((void**)&phi, g_Phi);
    cudaGetSymbolAddress((void**)&plo, g_Plo);
    cudaGetSymbolAddress((void**)&whi, g_Whi);

    cudaFuncSetAttribute(attn_kernel,
                         cudaFuncAttributeMaxDynamicSharedMemorySize, ATTN_SMEM_BYTES);
    cudaFuncSetAttribute(gemm_hmma,
                         cudaFuncAttributeMaxDynamicSharedMemorySize, HGEMM_SMEM);

    const int NX = MROWS * CH;
    const int NW = CH * CH;

    split_f16<<<NX / 1024, 256>>>(x, ahi, alo, NX);
    to_f16<<<NW / 1024, 256>>>(Wq, whi + 0 * (size_t)NW, NW);
    to_f16<<<NW / 1024, 256>>>(Wk, whi + 1 * (size_t)NW, NW);
    to_f16<<<NW / 1024, 256>>>(Wv, whi + 2 * (size_t)NW, NW);
    to_f16<<<NW / 1024, 256>>>(Wo, whi + 3 * (size_t)NW, NW);

    dim3 ggrid(CH / 128, MROWS / 128);   // (8, 128)
    gemm_hmma<<<ggrid, 256, HGEMM_SMEM>>>(ahi, alo, whi + 0 * (size_t)NW, bq, qp);
    gemm_hmma<<<ggrid, 256, HGEMM_SMEM>>>(ahi, alo, whi + 1 * (size_t)NW, bk, kp);
    gemm_hmma<<<ggrid, 256, HGEMM_SMEM>>>(ahi, alo, whi + 2 * (size_t)NW, bv, vp);

    attn_kernel<<<dim3(NB, NH, BATCH), 256, ATTN_SMEM_BYTES>>>(qp, kp, vp, phi, plo);

    gemm_hmma<<<ggrid, 256, HGEMM_SMEM>>>(phi, plo, whi + 3 * (size_t)NW, bo, out);
}

// round 7
// speedup vs baseline: 1.1224x; 1.0132x over previous
#include <cuda_runtime.h>
#include <cuda_fp16.h>
#include <cstdint>

#define BATCH 4
#define SEQ   4096
#define CH    1024
#define NH    16
#define HD    64
#define BS    64
#define NB    (SEQ / BS)          // 64
#define MROWS (BATCH * SEQ)       // 16384

// ---------------- scratch (device globals: allocation-free) ----------------
__device__ float g_Q[(size_t)MROWS * CH];
__device__ float g_K[(size_t)MROWS * CH];
__device__ float g_V[(size_t)MROWS * CH];
__device__ __half g_Ahi[(size_t)MROWS * CH];
__device__ __half g_Alo[(size_t)MROWS * CH];
__device__ __half g_Phi[(size_t)MROWS * CH];
__device__ __half g_Plo[(size_t)MROWS * CH];
__device__ __half g_Whi[(size_t)4 * CH * CH];

// =================== helpers ===================
__device__ __forceinline__ uint32_t smem_u32(const void* p) {
    uint32_t a;
    asm("{ .reg .u64 t; cvta.to.shared.u64 t, %1; cvt.u32.u64 %0, t; }"
        : "=r"(a) : "l"(p));
    return a;
}
__device__ __forceinline__ void cp16(uint32_t dst, const void* src) {
    asm volatile("cp.async.cg.shared.global [%0], [%1], 16;" :: "r"(dst), "l"(src));
}
__device__ __forceinline__ void cp_commit() {
    asm volatile("cp.async.commit_group;" ::: "memory");
}
template <int N>
__device__ __forceinline__ void cp_wait() {
    asm volatile("cp.async.wait_group %0;" :: "n"(N) : "memory");
}
__device__ __forceinline__ void ldsm4(uint32_t& r0, uint32_t& r1, uint32_t& r2,
                                      uint32_t& r3, uint32_t addr) {
    asm volatile("ldmatrix.sync.aligned.m8n8.x4.shared.b16 {%0,%1,%2,%3}, [%4];"
                 : "=r"(r0), "=r"(r1), "=r"(r2), "=r"(r3) : "r"(addr));
}
__device__ __forceinline__ void mma16816(float* c, const uint32_t* a,
                                         uint32_t b0, uint32_t b1) {
    asm volatile(
        "mma.sync.aligned.m16n8k16.row.col.f32.f16.f16.f32 "
        "{%0,%1,%2,%3}, {%4,%5,%6,%7}, {%8,%9}, {%0,%1,%2,%3};"
        : "+f"(c[0]), "+f"(c[1]), "+f"(c[2]), "+f"(c[3])
        : "r"(a[0]), "r"(a[1]), "r"(a[2]), "r"(a[3]), "r"(b0), "r"(b1));
}

// =================== fp32 -> fp16 hi/lo splitter ===================
__global__ __launch_bounds__(256) void split_f16(
    const float* __restrict__ in, __half* __restrict__ hi,
    __half* __restrict__ lo, int n)
{
    int i = (blockIdx.x * 256 + threadIdx.x) * 4;
    if (i >= n) return;
    float4 v = *(const float4*)(in + i);
    __half h0 = __float2half(v.x);
    __half h1 = __float2half(v.y);
    __half h2 = __float2half(v.z);
    __half h3 = __float2half(v.w);
    __half2 hp0; hp0.x = h0; hp0.y = h1;
    __half2 hp1; hp1.x = h2; hp1.y = h3;
    __half2 lp0; lp0.x = __float2half(v.x - __half2float(h0));
    lp0.y = __float2half(v.y - __half2float(h1));
    __half2 lp1; lp1.x = __float2half(v.z - __half2float(h2));
    lp1.y = __float2half(v.w - __half2float(h3));
    *(__half2*)(hi + i)     = hp0;
    *(__half2*)(hi + i + 2) = hp1;
    *(__half2*)(lo + i)     = lp0;
    *(__half2*)(lo + i + 2) = lp1;
}
// all 4 weight matrices in one launch; whi is contiguous [4][CH*CH]
__global__ __launch_bounds__(256) void to_f16_w4(
    const float* __restrict__ w0, const float* __restrict__ w1,
    const float* __restrict__ w2, const float* __restrict__ w3,
    __half* __restrict__ hi)
{
    const int seg = blockIdx.x >> 10;            // 0..3
    const int loc = (int)(blockIdx.x & 1023) * 1024 + threadIdx.x * 4;
    const float* in = (seg == 0) ? w0 : (seg == 1) ? w1 : (seg == 2) ? w2 : w3;
    float4 v = *(const float4*)(in + loc);
    __half2 hp0; hp0.x = __float2half(v.x); hp0.y = __float2half(v.y);
    __half2 hp1; hp1.x = __float2half(v.z); hp1.y = __float2half(v.w);
    __half* out = hi + (size_t)seg * CH * CH + loc;
    *(__half2*)(out)     = hp0;
    *(__half2*)(out + 2) = hp1;
}

// =================== HMMA GEMM core (BM=BN=128, BK=32, 8 warps) =============
#define BKH 32
#define NKC (CH / BKH)            // 32
#define HT_BYTES 8192             // 128 rows * 64B
#define HSTAGE (3 * HT_BYTES)     // Ahi, Alo, Bh
#define HGEMM_SMEM (3 * HSTAGE)   // 73728

__device__ __forceinline__ uint32_t sw_off(int row, int chunk) {
    return (uint32_t)(row * 64 + ((chunk ^ ((row >> 1) & 3)) << 4));
}

__device__ __forceinline__ void gemm_body(
    const __half* __restrict__ Ahi_t, const __half* __restrict__ Alo_t,
    const __half* __restrict__ Bh_t,
    const float* __restrict__ bias, float* __restrict__ Out,
    int bm, int bn, char* dsm)
{
    const uint32_t base = smem_u32(dsm);
    const int tid  = threadIdx.x;
    const int wid  = tid >> 5;
    const int lane = tid & 31;
    const int wm = (wid & 3) * 32;
    const int wn = (wid >> 2) * 64;

    const __half* srcs[3] = { Ahi_t, Alo_t, Bh_t };

    auto load_stage = [&](int st, int kc) {
        const uint32_t sb = base + st * HSTAGE;
#pragma unroll
        for (int p = 0; p < 6; p++) {
            int idx = p * 256 + tid;       // 0..1535
            int buf = idx >> 9;            // 0..2
            int rem = idx & 511;
            int row = rem >> 2;            // 0..127
            int ch  = rem & 3;
            const __half* s = srcs[buf] + (size_t)row * CH + kc * BKH + ch * 8;
            cp16(sb + buf * HT_BYTES + sw_off(row, ch), s);
        }
        cp_commit();
    };

    float acc[2][8][4];
#pragma unroll
    for (int mi = 0; mi < 2; mi++)
#pragma unroll
        for (int ni = 0; ni < 8; ni++)
#pragma unroll
            for (int t = 0; t < 4; t++) acc[mi][ni][t] = 0.0f;

    load_stage(0, 0);
    load_stage(1, 1);

    const int lr = lane & 15;
    const int lc = lane >> 4;

    for (int kc = 0; kc < NKC; kc++) {
        if (kc < NKC - 1) cp_wait<1>(); else cp_wait<0>();
        __syncthreads();

        const uint32_t sb = base + (kc % 3) * HSTAGE;
        const uint32_t aHib = sb;
        const uint32_t aLob = sb + HT_BYTES;
        const uint32_t bHib = sb + 2 * HT_BYTES;

#pragma unroll
        for (int ks = 0; ks < 2; ks++) {
            const int chnk = ks * 2 + lc;
            uint32_t ah[2][4], al[2][4], bh[4][4];
#pragma unroll
            for (int mi = 0; mi < 2; mi++) {
                uint32_t off = sw_off(wm + mi * 16 + lr, chnk);
                ldsm4(ah[mi][0], ah[mi][1], ah[mi][2], ah[mi][3], aHib + off);
                ldsm4(al[mi][0], al[mi][1], al[mi][2], al[mi][3], aLob + off);
            }
#pragma unroll
            for (int g = 0; g < 4; g++) {
                uint32_t off = sw_off(wn + g * 16 + lr, chnk);
                ldsm4(bh[g][0], bh[g][1], bh[g][2], bh[g][3], bHib + off);
            }
#pragma unroll
            for (int mi = 0; mi < 2; mi++)
#pragma unroll
                for (int ni = 0; ni < 8; ni++) {
                    const int g = ni >> 1, w = ni & 1;
                    mma16816(acc[mi][ni], ah[mi], bh[g][w], bh[g][w + 2]);
                    mma16816(acc[mi][ni], al[mi], bh[g][w], bh[g][w + 2]);
                }
        }
        if (kc + 2 < NKC) load_stage((kc + 2) % 3, kc + 2);
    }

#pragma unroll
    for (int mi = 0; mi < 2; mi++) {
        const int r0 = bm + wm + mi * 16 + (lane >> 2);
#pragma unroll
        for (int ni = 0; ni < 8; ni++) {
            const int c = bn + wn + ni * 8 + (lane & 3) * 2;
            const float b0 = bias[c], b1 = bias[c + 1];
            float2 v0 = make_float2(acc[mi][ni][0] + b0, acc[mi][ni][1] + b1);
            float2 v1 = make_float2(acc[mi][ni][2] + b0, acc[mi][ni][3] + b1);
            *(float2*)(Out + (size_t)r0 * CH + c)       = v0;
            *(float2*)(Out + (size_t)(r0 + 8) * CH + c) = v1;
        }
    }
}

// fused QKV GEMM: grid (24, 128); N-tile selects which of Q/K/V it belongs to
__global__ __launch_bounds__(256, 2) void gemm_qkv(
    const __half* __restrict__ Ahi, const __half* __restrict__ Alo,
    const __half* __restrict__ Wall,
    const float* __restrict__ bq, const float* __restrict__ bk,
    const float* __restrict__ bv,
    float* __restrict__ Qo, float* __restrict__ Ko, float* __restrict__ Vo)
{
    extern __shared__ char dsm[];
    const int bng = blockIdx.x * 128;        // 0..2944
    const int sel = bng >> 10;               // 0,1,2
    const int bn  = bng & 1023;
    const int bm  = blockIdx.y * 128;
    const float* bias = (sel == 0) ? bq : (sel == 1) ? bk : bv;
    float* Out = (sel == 0) ? Qo : (sel == 1) ? Ko : Vo;
    const __half* Bh = Wall + (size_t)sel * CH * CH + (size_t)bn * CH;
    gemm_body(Ahi + (size_t)bm * CH, Alo + (size_t)bm * CH, Bh, bias, Out, bm, bn, dsm);
}

// single GEMM (used for the output projection)
__global__ __launch_bounds__(256, 2) void gemm_hmma(
    const __half* __restrict__ Ahi, const __half* __restrict__ Alo,
    const __half* __restrict__ Bh,
    const float* __restrict__ bias, float* __restrict__ Out)
{
    extern __shared__ char dsm[];
    const int bm = blockIdx.y * 128;
    const int bn = blockIdx.x * 128;
    gemm_body(Ahi + (size_t)bm * CH, Alo + (size_t)bm * CH,
              Bh + (size_t)bn * CH, bias, Out, bm, bn, dsm);
}

// ---------------- attention: 128-col window (blocks n-1, n only) -----------
#define QT_STRIDE 68
#define KT_STRIDE 132
#define VS_STRIDE 68
#define PS_STRIDE 132
#define WIN 128
#define QT_OFF 0
#define KV_OFF (64 * QT_STRIDE)
#define KV_FLOATS 8704
#define PS_OFF (KV_OFF + KV_FLOATS)
#define SMEM_FLOATS (PS_OFF + (64 * PS_STRIDE) / 2)
#define ATTN_SMEM_BYTES (SMEM_FLOATS * 4)         // 69120

__global__ __launch_bounds__(256, 2) void attn_kernel(
    const float* __restrict__ Q, const float* __restrict__ K,
    const float* __restrict__ V,
    __half* __restrict__ Ohi, __half* __restrict__ Olo)
{
    extern __shared__ float sm[];
    float*  qT  = sm + QT_OFF;
    float*  kT  = sm + KV_OFF;
    float*  vs  = sm + KV_OFF;
    __half* Ps  = (__half*)(sm + PS_OFF);

    const int tid = threadIdx.x;
    const int n = blockIdx.x;
    const int h = blockIdx.y;
    const int b = blockIdx.z;
    const size_t base = (size_t)b * SEQ * CH + (size_t)h * HD;

#pragma unroll
    for (int p = 0; p < 4; p++) {
        int idx = tid + p * 256;
        int i   = idx >> 4;
        int dd0 = (idx & 15) << 2;
        float4 v4 = *(const float4*)(Q + base + (size_t)(n * BS + i) * CH + dd0);
        qT[(dd0 + 0) * QT_STRIDE + i] = v4.x;
        qT[(dd0 + 1) * QT_STRIDE + i] = v4.y;
        qT[(dd0 + 2) * QT_STRIDE + i] = v4.z;
        qT[(dd0 + 3) * QT_STRIDE + i] = v4.w;
    }
#pragma unroll
    for (int p = 0; p < 8; p++) {
        int idx = tid + p * 256;
        int j   = idx >> 4;
        int dd0 = (idx & 15) << 2;
        int kpos = (n - 1) * BS + j;
        float4 v4 = make_float4(0.f, 0.f, 0.f, 0.f);
        if (kpos >= 0)
            v4 = *(const float4*)(K + base + (size_t)kpos * CH + dd0);
        kT[(dd0 + 0) * KT_STRIDE + j] = v4.x;
        kT[(dd0 + 1) * KT_STRIDE + j] = v4.y;
        kT[(dd0 + 2) * KT_STRIDE + j] = v4.z;
        kT[(dd0 + 3) * KT_STRIDE + j] = v4.w;
    }
    __syncthreads();

    const int i0 = (tid >> 4) << 2;
    const int j0 = (tid & 15) << 3;
    float acc[4][8];
#pragma unroll
    for (int ii = 0; ii < 4; ii++)
#pragma unroll
        for (int jj = 0; jj < 8; jj++) acc[ii][jj] = 0.0f;

#pragma unroll 4
    for (int dd = 0; dd < 64; dd++) {
        float4 a4 = *(const float4*)&qT[dd * QT_STRIDE + i0];
        float4 b0 = *(const float4*)&kT[dd * KT_STRIDE + j0];
        float4 b1 = *(const float4*)&kT[dd * KT_STRIDE + j0 + 4];
        float a[4] = {a4.x, a4.y, a4.z, a4.w};
        float bb[8] = {b0.x, b0.y, b0.z, b0.w, b1.x, b1.y, b1.z, b1.w};
#pragma unroll
        for (int ii = 0; ii < 4; ii++)
#pragma unroll
            for (int jj = 0; jj < 8; jj++)
                acc[ii][jj] += a[ii] * bb[jj];
    }

    const float scale = 0.125f;
    float mrow[4] = {-1e30f, -1e30f, -1e30f, -1e30f};
#pragma unroll
    for (int ii = 0; ii < 4; ii++) {
        const int i = i0 + ii;
#pragma unroll
        for (int jj = 0; jj < 8; jj++) {
            const int j = j0 + jj;
            bool valid = (j <= i + BS) && (n > 0 || j >= BS);
            acc[ii][jj] = valid ? acc[ii][jj] * scale : -1e30f;
            mrow[ii] = fmaxf(mrow[ii], acc[ii][jj]);
        }
    }
#pragma unroll
    for (int ii = 0; ii < 4; ii++) {
        mrow[ii] = fmaxf(mrow[ii], __shfl_xor_sync(0xffffffffu, mrow[ii], 1));
        mrow[ii] = fmaxf(mrow[ii], __shfl_xor_sync(0xffffffffu, mrow[ii], 2));
        mrow[ii] = fmaxf(mrow[ii], __shfl_xor_sync(0xffffffffu, mrow[ii], 4));
        mrow[ii] = fmaxf(mrow[ii], __shfl_xor_sync(0xffffffffu, mrow[ii], 8));
    }
    float srow[4] = {0.f, 0.f, 0.f, 0.f};
#pragma unroll
    for (int ii = 0; ii < 4; ii++)
#pragma unroll
        for (int jj = 0; jj < 8; jj++) {
            acc[ii][jj] = __expf(acc[ii][jj] - mrow[ii]);
            srow[ii] += acc[ii][jj];
        }
#pragma unroll
    for (int ii = 0; ii < 4; ii++) {
        srow[ii] += __shfl_xor_sync(0xffffffffu, srow[ii], 1);
        srow[ii] += __shfl_xor_sync(0xffffffffu, srow[ii], 2);
        srow[ii] += __shfl_xor_sync(0xffffffffu, srow[ii], 4);
        srow[ii] += __shfl_xor_sync(0xffffffffu, srow[ii], 8);
        const float inv = 1.0f / srow[ii];
#pragma unroll
        for (int jj = 0; jj < 8; jj++)
            Ps[(i0 + ii) * PS_STRIDE + j0 + jj] = __float2half(acc[ii][jj] * inv);
    }
    __syncthreads();

#pragma unroll
    for (int p = 0; p < 8; p++) {
        int idx = tid + p * 256;
        int j   = idx >> 4;
        int dd0 = (idx & 15) << 2;
        int kpos = (n - 1) * BS + j;
        float4 v4 = make_float4(0.f, 0.f, 0.f, 0.f);
        if (kpos >= 0)
            v4 = *(const float4*)(V + base + (size_t)kpos * CH + dd0);
        *(float4*)&vs[j * VS_STRIDE + dd0] = v4;
    }
    __syncthreads();

    const int c0 = (tid & 15) << 2;
    float o[4][4];
#pragma unroll
    for (int ii = 0; ii < 4; ii++)
#pragma unroll
        for (int cc = 0; cc < 4; cc++) o[ii][cc] = 0.0f;

    const int jlim = (i0 + 68 < WIN) ? (i0 + 68) : WIN;
#pragma unroll 4
    for (int j = 0; j < jlim; j++) {
        float4 v4 = *(const float4*)&vs[j * VS_STRIDE + c0];
        float p0 = __half2float(Ps[(i0 + 0) * PS_STRIDE + j]);
        float p1 = __half2float(Ps[(i0 + 1) * PS_STRIDE + j]);
        float p2 = __half2float(Ps[(i0 + 2) * PS_STRIDE + j]);
        float p3 = __half2float(Ps[(i0 + 3) * PS_STRIDE + j]);
        o[0][0] += p0 * v4.x; o[0][1] += p0 * v4.y; o[0][2] += p0 * v4.z; o[0][3] += p0 * v4.w;
        o[1][0] += p1 * v4.x; o[1][1] += p1 * v4.y; o[1][2] += p1 * v4.z; o[1][3] += p1 * v4.w;
        o[2][0] += p2 * v4.x; o[2][1] += p2 * v4.y; o[2][2] += p2 * v4.z; o[2][3] += p2 * v4.w;
        o[3][0] += p3 * v4.x; o[3][1] += p3 * v4.y; o[3][2] += p3 * v4.z; o[3][3] += p3 * v4.w;
    }
#pragma unroll
    for (int ii = 0; ii < 4; ii++) {
        const size_t oidx = base + (size_t)(n * BS + i0 + ii) * CH + c0;
        __half h0 = __float2half(o[ii][0]);
        __half h1 = __float2half(o[ii][1]);
        __half h2 = __float2half(o[ii][2]);
        __half h3 = __float2half(o[ii][3]);
        __half2 hp0; hp0.x = h0; hp0.y = h1;
        __half2 hp1; hp1.x = h2; hp1.y = h3;
        __half2 lp0, lp1;
        lp0.x = __float2half(o[ii][0] - __half2float(h0));
        lp0.y = __float2half(o[ii][1] - __half2float(h1));
        lp1.x = __float2half(o[ii][2] - __half2float(h2));
        lp1.y = __float2half(o[ii][3] - __half2float(h3));
        *(__half2*)(Ohi + oidx)     = hp0;
        *(__half2*)(Ohi + oidx + 2) = hp1;
        *(__half2*)(Olo + oidx)     = lp0;
        *(__half2*)(Olo + oidx + 2) = lp1;
    }
}

// ---------------------------------------------------------------------------
extern "C" void kernel_launch(void* const* d_in, const int* in_sizes, int n_in,
                              void* d_out, int out_size)
{
    const float* x  = (const float*)d_in[0];
    const float* Wq = (const float*)d_in[1];
    const float* bq = (const float*)d_in[2];
    const float* Wk = (const float*)d_in[3];
    const float* bk = (const float*)d_in[4];
    const float* Wv = (const float*)d_in[5];
    const float* bv = (const float*)d_in[6];
    const float* Wo = (const float*)d_in[7];
    const float* bo = (const float*)d_in[8];
    float* out = (float*)d_out;

    float *qp, *kp, *vp;
    __half *ahi, *alo, *phi, *plo, *whi;
    cudaGetSymbolAddress((void**)&qp,  g_Q);
    cudaGetSymbolAddress((void**)&kp,  g_K);
    cudaGetSymbolAddress((void**)&vp,  g_V);
    cudaGetSymbolAddress((void**)&ahi, g_Ahi);
    cudaGetSymbolAddress((void**)&alo, g_Alo);
    cudaGetSymbolAddress((void**)&phi, g_Phi);
    cudaGetSymbolAddress((void**)&plo, g_Plo);
    cudaGetSymbolAddress((void**)&whi, g_Whi);

    cudaFuncSetAttribute(attn_kernel,
                         cudaFuncAttributeMaxDynamicSharedMemorySize, ATTN_SMEM_BYTES);
    cudaFuncSetAttribute(gemm_hmma,
                         cudaFuncAttributeMaxDynamicSharedMemorySize, HGEMM_SMEM);
    cudaFuncSetAttribute(gemm_qkv,
                         cudaFuncAttributeMaxDynamicSharedMemorySize, HGEMM_SMEM);

    const int NX = MROWS * CH;
    const int NW = CH * CH;

    split_f16<<<NX / 1024, 256>>>(x, ahi, alo, NX);
    to_f16_w4<<<4096, 256>>>(Wq, Wk, Wv, Wo, whi);

    gemm_qkv<<<dim3(24, MROWS / 128), 256, HGEMM_SMEM>>>(
        ahi, alo, whi, bq, bk, bv, qp, kp, vp);

    attn_kernel<<<dim3(NB, NH, BATCH), 256, ATTN_SMEM_BYTES>>>(qp, kp, vp, phi, plo);

    gemm_hmma<<<dim3(8, MROWS / 128), 256, HGEMM_SMEM>>>(
        phi, plo, whi + 3 * (size_t)NW, bo, out);
}

// round 8
// speedup vs baseline: 1.1524x; 1.0267x over previous
#include <cuda_runtime.h>
#include <cuda_fp16.h>
#include <cstdint>

#define BATCH 4
#define SEQ   4096
#define CH    1024
#define NH    16
#define HD    64
#define BS    64
#define NB    (SEQ / BS)          // 64
#define MROWS (BATCH * SEQ)       // 16384

// ---------------- scratch (device globals: allocation-free) ----------------
__device__ float g_Q[(size_t)MROWS * CH];
__device__ float g_K[(size_t)MROWS * CH];
__device__ float g_V[(size_t)MROWS * CH];
__device__ __half g_Ahi[(size_t)MROWS * CH];
__device__ __half g_Alo[(size_t)MROWS * CH];
__device__ __half g_Phi[(size_t)MROWS * CH];
__device__ __half g_Plo[(size_t)MROWS * CH];
__device__ __half g_Whi[(size_t)4 * CH * CH];

// =================== helpers ===================
__device__ __forceinline__ uint32_t smem_u32(const void* p) {
    uint32_t a;
    asm("{ .reg .u64 t; cvta.to.shared.u64 t, %1; cvt.u32.u64 %0, t; }"
        : "=r"(a) : "l"(p));
    return a;
}
__device__ __forceinline__ void cp16(uint32_t dst, const void* src) {
    asm volatile("cp.async.cg.shared.global [%0], [%1], 16;" :: "r"(dst), "l"(src));
}
__device__ __forceinline__ void cp_commit() {
    asm volatile("cp.async.commit_group;" ::: "memory");
}
template <int N>
__device__ __forceinline__ void cp_wait() {
    asm volatile("cp.async.wait_group %0;" :: "n"(N) : "memory");
}
__device__ __forceinline__ void ldsm4(uint32_t& r0, uint32_t& r1, uint32_t& r2,
                                      uint32_t& r3, uint32_t addr) {
    asm volatile("ldmatrix.sync.aligned.m8n8.x4.shared.b16 {%0,%1,%2,%3}, [%4];"
                 : "=r"(r0), "=r"(r1), "=r"(r2), "=r"(r3) : "r"(addr));
}
__device__ __forceinline__ void mma16816(float* c, const uint32_t* a,
                                         uint32_t b0, uint32_t b1) {
    asm volatile(
        "mma.sync.aligned.m16n8k16.row.col.f32.f16.f16.f32 "
        "{%0,%1,%2,%3}, {%4,%5,%6,%7}, {%8,%9}, {%0,%1,%2,%3};"
        : "+f"(c[0]), "+f"(c[1]), "+f"(c[2]), "+f"(c[3])
        : "r"(a[0]), "r"(a[1]), "r"(a[2]), "r"(a[3]), "r"(b0), "r"(b1));
}

// =================== fp32 -> fp16 hi/lo splitter ===================
__global__ __launch_bounds__(256) void split_f16(
    const float* __restrict__ in, __half* __restrict__ hi,
    __half* __restrict__ lo, int n)
{
    int i = (blockIdx.x * 256 + threadIdx.x) * 4;
    if (i >= n) return;
    float4 v = *(const float4*)(in + i);
    __half h0 = __float2half(v.x);
    __half h1 = __float2half(v.y);
    __half h2 = __float2half(v.z);
    __half h3 = __float2half(v.w);
    __half2 hp0; hp0.x = h0; hp0.y = h1;
    __half2 hp1; hp1.x = h2; hp1.y = h3;
    __half2 lp0; lp0.x = __float2half(v.x - __half2float(h0));
    lp0.y = __float2half(v.y - __half2float(h1));
    __half2 lp1; lp1.x = __float2half(v.z - __half2float(h2));
    lp1.y = __float2half(v.w - __half2float(h3));
    *(__half2*)(hi + i)     = hp0;
    *(__half2*)(hi + i + 2) = hp1;
    *(__half2*)(lo + i)     = lp0;
    *(__half2*)(lo + i + 2) = lp1;
}
__global__ __launch_bounds__(256) void to_f16_w4(
    const float* __restrict__ w0, const float* __restrict__ w1,
    const float* __restrict__ w2, const float* __restrict__ w3,
    __half* __restrict__ hi)
{
    const int seg = blockIdx.x >> 10;
    const int loc = (int)(blockIdx.x & 1023) * 1024 + threadIdx.x * 4;
    const float* in = (seg == 0) ? w0 : (seg == 1) ? w1 : (seg == 2) ? w2 : w3;
    float4 v = *(const float4*)(in + loc);
    __half2 hp0; hp0.x = __float2half(v.x); hp0.y = __float2half(v.y);
    __half2 hp1; hp1.x = __float2half(v.z); hp1.y = __float2half(v.w);
    __half* out = hi + (size_t)seg * CH * CH + loc;
    *(__half2*)(out)     = hp0;
    *(__half2*)(out + 2) = hp1;
}

// =================== HMMA GEMM core (BM=BN=128, BK=32, 8 warps) =============
#define BKH 32
#define NKC (CH / BKH)            // 32
#define HT_BYTES 8192
#define HSTAGE (3 * HT_BYTES)
#define HGEMM_SMEM (3 * HSTAGE)   // 73728

__device__ __forceinline__ uint32_t sw_off(int row, int chunk) {
    return (uint32_t)(row * 64 + ((chunk ^ ((row >> 1) & 3)) << 4));
}

__device__ __forceinline__ void gemm_body(
    const __half* __restrict__ Ahi_t, const __half* __restrict__ Alo_t,
    const __half* __restrict__ Bh_t,
    const float* __restrict__ bias, float* __restrict__ Out,
    int bm, int bn, char* dsm)
{
    const uint32_t base = smem_u32(dsm);
    const int tid  = threadIdx.x;
    const int wid  = tid >> 5;
    const int lane = tid & 31;
    const int wm = (wid & 3) * 32;
    const int wn = (wid >> 2) * 64;

    const __half* srcs[3] = { Ahi_t, Alo_t, Bh_t };

    auto load_stage = [&](int st, int kc) {
        const uint32_t sb = base + st * HSTAGE;
#pragma unroll
        for (int p = 0; p < 6; p++) {
            int idx = p * 256 + tid;
            int buf = idx >> 9;
            int rem = idx & 511;
            int row = rem >> 2;
            int ch  = rem & 3;
            const __half* s = srcs[buf] + (size_t)row * CH + kc * BKH + ch * 8;
            cp16(sb + buf * HT_BYTES + sw_off(row, ch), s);
        }
        cp_commit();
    };

    float acc[2][8][4];
#pragma unroll
    for (int mi = 0; mi < 2; mi++)
#pragma unroll
        for (int ni = 0; ni < 8; ni++)
#pragma unroll
            for (int t = 0; t < 4; t++) acc[mi][ni][t] = 0.0f;

    load_stage(0, 0);
    load_stage(1, 1);

    const int lr = lane & 15;
    const int lc = lane >> 4;

    for (int kc = 0; kc < NKC; kc++) {
        if (kc < NKC - 1) cp_wait<1>(); else cp_wait<0>();
        __syncthreads();

        const uint32_t sb = base + (kc % 3) * HSTAGE;
        const uint32_t aHib = sb;
        const uint32_t aLob = sb + HT_BYTES;
        const uint32_t bHib = sb + 2 * HT_BYTES;

#pragma unroll
        for (int ks = 0; ks < 2; ks++) {
            const int chnk = ks * 2 + lc;
            uint32_t ah[2][4], al[2][4], bh[4][4];
#pragma unroll
            for (int mi = 0; mi < 2; mi++) {
                uint32_t off = sw_off(wm + mi * 16 + lr, chnk);
                ldsm4(ah[mi][0], ah[mi][1], ah[mi][2], ah[mi][3], aHib + off);
                ldsm4(al[mi][0], al[mi][1], al[mi][2], al[mi][3], aLob + off);
            }
#pragma unroll
            for (int g = 0; g < 4; g++) {
                uint32_t off = sw_off(wn + g * 16 + lr, chnk);
                ldsm4(bh[g][0], bh[g][1], bh[g][2], bh[g][3], bHib + off);
            }
#pragma unroll
            for (int mi = 0; mi < 2; mi++)
#pragma unroll
                for (int ni = 0; ni < 8; ni++) {
                    const int g = ni >> 1, w = ni & 1;
                    mma16816(acc[mi][ni], ah[mi], bh[g][w], bh[g][w + 2]);
                    mma16816(acc[mi][ni], al[mi], bh[g][w], bh[g][w + 2]);
                }
        }
        if (kc + 2 < NKC) load_stage((kc + 2) % 3, kc + 2);
    }

#pragma unroll
    for (int mi = 0; mi < 2; mi++) {
        const int r0 = bm + wm + mi * 16 + (lane >> 2);
#pragma unroll
        for (int ni = 0; ni < 8; ni++) {
            const int c = bn + wn + ni * 8 + (lane & 3) * 2;
            const float b0 = bias[c], b1 = bias[c + 1];
            float2 v0 = make_float2(acc[mi][ni][0] + b0, acc[mi][ni][1] + b1);
            float2 v1 = make_float2(acc[mi][ni][2] + b0, acc[mi][ni][3] + b1);
            *(float2*)(Out + (size_t)r0 * CH + c)       = v0;
            *(float2*)(Out + (size_t)(r0 + 8) * CH + c) = v1;
        }
    }
}

__global__ __launch_bounds__(256, 2) void gemm_qkv(
    const __half* __restrict__ Ahi, const __half* __restrict__ Alo,
    const __half* __restrict__ Wall,
    const float* __restrict__ bq, const float* __restrict__ bk,
    const float* __restrict__ bv,
    float* __restrict__ Qo, float* __restrict__ Ko, float* __restrict__ Vo)
{
    extern __shared__ char dsm[];
    const int bng = blockIdx.x * 128;
    const int sel = bng >> 10;
    const int bn  = bng & 1023;
    const int bm  = blockIdx.y * 128;
    const float* bias = (sel == 0) ? bq : (sel == 1) ? bk : bv;
    float* Out = (sel == 0) ? Qo : (sel == 1) ? Ko : Vo;
    const __half* Bh = Wall + (size_t)sel * CH * CH + (size_t)bn * CH;
    gemm_body(Ahi + (size_t)bm * CH, Alo + (size_t)bm * CH, Bh, bias, Out, bm, bn, dsm);
}

__global__ __launch_bounds__(256, 2) void gemm_hmma(
    const __half* __restrict__ Ahi, const __half* __restrict__ Alo,
    const __half* __restrict__ Bh,
    const float* __restrict__ bias, float* __restrict__ Out)
{
    extern __shared__ char dsm[];
    const int bm = blockIdx.y * 128;
    const int bn = blockIdx.x * 128;
    gemm_body(Ahi + (size_t)bm * CH, Alo + (size_t)bm * CH,
              Bh + (size_t)bn * CH, bias, Out, bm, bn, dsm);
}

// ---------------- attention: 128-col window (blocks n-1, n only) -----------
#define QT_STRIDE 68
#define KT_STRIDE 132
#define VS_STRIDE 68
#define PS_STRIDE 132
#define WIN 128
#define QT_OFF 0
#define KV_OFF (64 * QT_STRIDE)
#define KV_FLOATS 8704
#define PS_OFF (KV_OFF + KV_FLOATS)
#define SMEM_FLOATS (PS_OFF + (64 * PS_STRIDE) / 2)
#define ATTN_SMEM_BYTES (SMEM_FLOATS * 4)         // 69120

__global__ __launch_bounds__(256, 2) void attn_kernel(
    const float* __restrict__ Q, const float* __restrict__ K,
    const float* __restrict__ V,
    __half* __restrict__ Ohi, __half* __restrict__ Olo)
{
    extern __shared__ float sm[];
    float*  qT  = sm + QT_OFF;
    float*  kT  = sm + KV_OFF;
    float*  vs  = sm + KV_OFF;
    __half* Ps  = (__half*)(sm + PS_OFF);

    const int tid  = threadIdx.x;
    const int warp = tid >> 5;
    const int lane = tid & 31;
    const int n = blockIdx.x;
    const int h = blockIdx.y;
    const int b = blockIdx.z;
    const size_t base = (size_t)b * SEQ * CH + (size_t)h * HD;

#pragma unroll
    for (int p = 0; p < 4; p++) {
        int idx = tid + p * 256;
        int i   = idx >> 4;
        int dd0 = (idx & 15) << 2;
        float4 v4 = *(const float4*)(Q + base + (size_t)(n * BS + i) * CH + dd0);
        qT[(dd0 + 0) * QT_STRIDE + i] = v4.x;
        qT[(dd0 + 1) * QT_STRIDE + i] = v4.y;
        qT[(dd0 + 2) * QT_STRIDE + i] = v4.z;
        qT[(dd0 + 3) * QT_STRIDE + i] = v4.w;
    }
#pragma unroll
    for (int p = 0; p < 8; p++) {
        int idx = tid + p * 256;
        int j   = idx >> 4;
        int dd0 = (idx & 15) << 2;
        int kpos = (n - 1) * BS + j;
        float4 v4 = make_float4(0.f, 0.f, 0.f, 0.f);
        if (kpos >= 0)
            v4 = *(const float4*)(K + base + (size_t)kpos * CH + dd0);
        kT[(dd0 + 0) * KT_STRIDE + j] = v4.x;
        kT[(dd0 + 1) * KT_STRIDE + j] = v4.y;
        kT[(dd0 + 2) * KT_STRIDE + j] = v4.z;
        kT[(dd0 + 3) * KT_STRIDE + j] = v4.w;
    }
    __syncthreads();

    // ---- score: warp owns 8 rows (i0=warp*8), lane owns 4 cols (j0=lane*4)
    const int i0 = warp << 3;
    const int j0 = lane << 2;
    float acc[8][4];
#pragma unroll
    for (int ii = 0; ii < 8; ii++)
#pragma unroll
        for (int jj = 0; jj < 4; jj++) acc[ii][jj] = 0.0f;

#pragma unroll 4
    for (int dd = 0; dd < 64; dd++) {
        float4 a0 = *(const float4*)&qT[dd * QT_STRIDE + i0];      // broadcast
        float4 a1 = *(const float4*)&qT[dd * QT_STRIDE + i0 + 4];  // broadcast
        float4 b4 = *(const float4*)&kT[dd * KT_STRIDE + j0];
        float a[8] = {a0.x, a0.y, a0.z, a0.w, a1.x, a1.y, a1.z, a1.w};
        float bb[4] = {b4.x, b4.y, b4.z, b4.w};
#pragma unroll
        for (int ii = 0; ii < 8; ii++)
#pragma unroll
            for (int jj = 0; jj < 4; jj++)
                acc[ii][jj] += a[ii] * bb[jj];
    }

    const float scale = 0.125f;
    float mrow[8];
#pragma unroll
    for (int ii = 0; ii < 8; ii++) {
        const int i = i0 + ii;
        mrow[ii] = -1e30f;
#pragma unroll
        for (int jj = 0; jj < 4; jj++) {
            const int j = j0 + jj;
            bool valid = (j <= i + BS) && (n > 0 || j >= BS);
            acc[ii][jj] = valid ? acc[ii][jj] * scale : -1e30f;
            mrow[ii] = fmaxf(mrow[ii], acc[ii][jj]);
        }
    }
#pragma unroll
    for (int ii = 0; ii < 8; ii++) {
        mrow[ii] = fmaxf(mrow[ii], __shfl_xor_sync(0xffffffffu, mrow[ii], 1));
        mrow[ii] = fmaxf(mrow[ii], __shfl_xor_sync(0xffffffffu, mrow[ii], 2));
        mrow[ii] = fmaxf(mrow[ii], __shfl_xor_sync(0xffffffffu, mrow[ii], 4));
        mrow[ii] = fmaxf(mrow[ii], __shfl_xor_sync(0xffffffffu, mrow[ii], 8));
        mrow[ii] = fmaxf(mrow[ii], __shfl_xor_sync(0xffffffffu, mrow[ii], 16));
    }
    float srow[8];
#pragma unroll
    for (int ii = 0; ii < 8; ii++) {
        srow[ii] = 0.f;
#pragma unroll
        for (int jj = 0; jj < 4; jj++) {
            acc[ii][jj] = __expf(acc[ii][jj] - mrow[ii]);
            srow[ii] += acc[ii][jj];
        }
    }
#pragma unroll
    for (int ii = 0; ii < 8; ii++) {
        srow[ii] += __shfl_xor_sync(0xffffffffu, srow[ii], 1);
        srow[ii] += __shfl_xor_sync(0xffffffffu, srow[ii], 2);
        srow[ii] += __shfl_xor_sync(0xffffffffu, srow[ii], 4);
        srow[ii] += __shfl_xor_sync(0xffffffffu, srow[ii], 8);
        srow[ii] += __shfl_xor_sync(0xffffffffu, srow[ii], 16);
        const float inv = 1.0f / srow[ii];
        __half2 p01, p23;
        p01.x = __float2half(acc[ii][0] * inv);
        p01.y = __float2half(acc[ii][1] * inv);
        p23.x = __float2half(acc[ii][2] * inv);
        p23.y = __float2half(acc[ii][3] * inv);
        __half* prow = Ps + (i0 + ii) * PS_STRIDE + j0;
        *(__half2*)(prow)     = p01;
        *(__half2*)(prow + 2) = p23;
    }
    __syncthreads();

    // v window over kT region
#pragma unroll
    for (int p = 0; p < 8; p++) {
        int idx = tid + p * 256;
        int j   = idx >> 4;
        int dd0 = (idx & 15) << 2;
        int kpos = (n - 1) * BS + j;
        float4 v4 = make_float4(0.f, 0.f, 0.f, 0.f);
        if (kpos >= 0)
            v4 = *(const float4*)(V + base + (size_t)kpos * CH + dd0);
        *(float4*)&vs[j * VS_STRIDE + dd0] = v4;
    }
    __syncthreads();

    // ---- PV: 4 rows per 16-thread group (unchanged layout)
    const int i0p = (tid >> 4) << 2;
    const int c0  = (tid & 15) << 2;
    float o[4][4];
#pragma unroll
    for (int ii = 0; ii < 4; ii++)
#pragma unroll
        for (int cc = 0; cc < 4; cc++) o[ii][cc] = 0.0f;

    const int jlim = (i0p + 68 < WIN) ? (i0p + 68) : WIN;
#pragma unroll 4
    for (int j = 0; j < jlim; j++) {
        float4 v4 = *(const float4*)&vs[j * VS_STRIDE + c0];
        float p0 = __half2float(Ps[(i0p + 0) * PS_STRIDE + j]);
        float p1 = __half2float(Ps[(i0p + 1) * PS_STRIDE + j]);
        float p2 = __half2float(Ps[(i0p + 2) * PS_STRIDE + j]);
        float p3 = __half2float(Ps[(i0p + 3) * PS_STRIDE + j]);
        o[0][0] += p0 * v4.x; o[0][1] += p0 * v4.y; o[0][2] += p0 * v4.z; o[0][3] += p0 * v4.w;
        o[1][0] += p1 * v4.x; o[1][1] += p1 * v4.y; o[1][2] += p1 * v4.z; o[1][3] += p1 * v4.w;
        o[2][0] += p2 * v4.x; o[2][1] += p2 * v4.y; o[2][2] += p2 * v4.z; o[2][3] += p2 * v4.w;
        o[3][0] += p3 * v4.x; o[3][1] += p3 * v4.y; o[3][2] += p3 * v4.z; o[3][3] += p3 * v4.w;
    }
#pragma unroll
    for (int ii = 0; ii < 4; ii++) {
        const size_t oidx = base + (size_t)(n * BS + i0p + ii) * CH + c0;
        __half h0 = __float2half(o[ii][0]);
        __half h1 = __float2half(o[ii][1]);
        __half h2 = __float2half(o[ii][2]);
        __half h3 = __float2half(o[ii][3]);
        __half2 hp0; hp0.x = h0; hp0.y = h1;
        __half2 hp1; hp1.x = h2; hp1.y = h3;
        __half2 lp0, lp1;
        lp0.x = __float2half(o[ii][0] - __half2float(h0));
        lp0.y = __float2half(o[ii][1] - __half2float(h1));
        lp1.x = __float2half(o[ii][2] - __half2float(h2));
        lp1.y = __float2half(o[ii][3] - __half2float(h3));
        *(__half2*)(Ohi + oidx)     = hp0;
        *(__half2*)(Ohi + oidx + 2) = hp1;
        *(__half2*)(Olo + oidx)     = lp0;
        *(__half2*)(Olo + oidx + 2) = lp1;
    }
}

// ---------------------------------------------------------------------------
extern "C" void kernel_launch(void* const* d_in, const int* in_sizes, int n_in,
                              void* d_out, int out_size)
{
    const float* x  = (const float*)d_in[0];
    const float* Wq = (const float*)d_in[1];
    const float* bq = (const float*)d_in[2];
    const float* Wk = (const float*)d_in[3];
    const float* bk = (const float*)d_in[4];
    const float* Wv = (const float*)d_in[5];
    const float* bv = (const float*)d_in[6];
    const float* Wo = (const float*)d_in[7];
    const float* bo = (const float*)d_in[8];
    float* out = (float*)d_out;

    float *qp, *kp, *vp;
    __half *ahi, *alo, *phi, *plo, *whi;
    cudaGetSymbolAddress((void**)&qp,  g_Q);
    cudaGetSymbolAddress((void**)&kp,  g_K);
    cudaGetSymbolAddress((void**)&vp,  g_V);
    cudaGetSymbolAddress((void**)&ahi, g_Ahi);
    cudaGetSymbolAddress((void**)&alo, g_Alo);
    cudaGetSymbolAddress((void**)&phi, g_Phi);
    cudaGetSymbolAddress((void**)&plo, g_Plo);
    cudaGetSymbolAddress((void**)&whi, g_Whi);

    cudaFuncSetAttribute(attn_kernel,
                         cudaFuncAttributeMaxDynamicSharedMemorySize, ATTN_SMEM_BYTES);
    cudaFuncSetAttribute(gemm_hmma,
                         cudaFuncAttributeMaxDynamicSharedMemorySize, HGEMM_SMEM);
    cudaFuncSetAttribute(gemm_qkv,
                         cudaFuncAttributeMaxDynamicSharedMemorySize, HGEMM_SMEM);

    const int NX = MROWS * CH;
    const int NW = CH * CH;

    split_f16<<<NX / 1024, 256>>>(x, ahi, alo, NX);
    to_f16_w4<<<4096, 256>>>(Wq, Wk, Wv, Wo, whi);

    gemm_qkv<<<dim3(24, MROWS / 128), 256, HGEMM_SMEM>>>(
        ahi, alo, whi, bq, bk, bv, qp, kp, vp);

    attn_kernel<<<dim3(NB, NH, BATCH), 256, ATTN_SMEM_BYTES>>>(qp, kp, vp, phi, plo);

    gemm_hmma<<<dim3(8, MROWS / 128), 256, HGEMM_SMEM>>>(
        phi, plo, whi + 3 * (size_t)NW, bo, out);
}